// round 3
// baseline (speedup 1.0000x reference)
#include <cuda_runtime.h>
#include <cstdint>

// CostVolume: cost[b,i,h,x] = (1/128) sum_c L[b,c,h,x]*R[b,c,h,x-i], 0 for x<i.
// b=8 c=128 h=96 w=320, 48 disparities. fp32.
// SIMT kernel with packed fma.rn.f32x2 (FFMA2), cp.async double buffering.
// One warp handles one (b,h,x0) unit: 128 x  x 48 i. Thread: 16 x  x 12 i.

typedef unsigned long long ull;

#define BB 8
#define CH 128
#define HH 96
#define WW 320
#define MAXD 48
#define PLANE (HH*WW)

#define NWARP 4                     // units per CTA
#define CC 8                        // channels per chunk
#define NCHUNK (CH/CC)              // 16
#define LROW 128                    // L floats per channel row
#define RROW 176                    // R floats per channel row [x0-48, x0+128)
#define STAGE_BYTES (CC*(LROW+RROW)*4)   // 9728
#define WARP_BYTES (2*STAGE_BYTES)       // 19456
#define SMEM_TOTAL (NWARP*WARP_BYTES)    // 77824

__device__ __forceinline__ uint32_t smem_u32(const void* p){
    uint32_t a;
    asm("{ .reg .u64 t; cvta.to.shared.u64 t, %1; cvt.u32.u64 %0, t; }" : "=r"(a) : "l"(p));
    return a;
}
__device__ __forceinline__ void cp16(uint32_t dst, const void* src, uint32_t sz){
    asm volatile("cp.async.ca.shared.global [%0], [%1], 16, %2;"
                 :: "r"(dst), "l"(src), "r"(sz) : "memory");
}
__device__ __forceinline__ ull pack2(float lo, float hi){
    ull d; asm("mov.b64 %0, {%1,%2};" : "=l"(d) : "f"(lo), "f"(hi)); return d;
}
__device__ __forceinline__ void fma2(ull& a, ull x, ull y){
    asm("fma.rn.f32x2 %0, %1, %2, %0;" : "+l"(a) : "l"(x), "l"(y));
}
__device__ __forceinline__ ull mul2(ull x, ull y){
    ull d; asm("mul.rn.f32x2 %0, %1, %2;" : "=l"(d) : "l"(x), "l"(y)); return d;
}

__global__ __launch_bounds__(128, 1)
void costvol_f32x2_kernel(const float* __restrict__ L,
                          const float* __restrict__ R,
                          float* __restrict__ out)
{
    extern __shared__ float smem[];
    const int tid  = threadIdx.x;
    const int w    = tid >> 5;
    const int lane = tid & 31;
    // lane = ig + 4*xq  -> each LDS.128 quarter-warp covers all 32 banks once
    const int xq = lane >> 2;       // 0..7  : x-hex (16 x per thread)
    const int ig = lane & 3;        // 0..3  : disparity group (12 i per thread)

    const int unit = blockIdx.x * NWARP + w;   // 2304 units
    const int xt = unit % 3;
    const int bh = unit / 3;
    const int h  = bh % HH;
    const int b  = bh / HH;
    const int x0 = xt * 96;         // tiles {0,96,192}, width 128; overlap recomputes
                                    // bitwise-identical values (benign same-value race)

    const float* Lbh = L + ((size_t)b * CH * HH + h) * WW;
    const float* Rbh = R + ((size_t)b * CH * HH + h) * WW;

    float* wsm = smem + (w * WARP_BYTES) / 4;
    const uint32_t wsu = smem_u32(wsm);

    const int X  = x0 + 16 * xq;    // first x of this thread
    const int i0 = 12 * ig;         // first disparity
    const int rb = 16 * xq - 12 * ig + 36;  // R-row float offset of window t=0

    // 96 packed accumulators: acc[a][u] = (cost(x=X+2u, i=i0+a), cost(x=X+2u+1, ...))
    ull acc[12][8];
    #pragma unroll
    for (int a = 0; a < 12; a++)
        #pragma unroll
        for (int u = 0; u < 8; u++) acc[a][u] = 0ULL;

    // ---- async load of one chunk: 608 x 16B cp.async, 19 per lane ----
    auto issue = [&](int k){
        const int c0 = k * CC;
        const uint32_t sb = wsu + (k & 1) * STAGE_BYTES;
        #pragma unroll
        for (int it = 0; it < 19; it++){
            int idx = lane + it * 32;       // 0..607
            int cc = idx / 76;
            int j  = idx - cc * 76;
            const float* gp;
            uint32_t dst, sz = 16;
            if (j < 32){                    // L row: 128 floats = 32 chunks
                gp  = Lbh + (size_t)(c0 + cc) * PLANE + x0 + 4 * j;
                dst = sb + cc * (LROW * 4) + 16 * j;
            } else {                        // R row: 176 floats = 44 chunks
                int jr = j - 32;
                int xr = x0 - 48 + 4 * jr;
                int xs = xr < 0 ? 0 : xr;
                gp  = Rbh + (size_t)(c0 + cc) * PLANE + xs;
                sz  = (xr >= 0) ? 16u : 0u; // zero-fill x' < 0
                dst = sb + CC * (LROW * 4) + cc * (RROW * 4) + 16 * jr;
            }
            cp16(dst, gp, sz);
        }
    };

    // ---- compute one chunk from smem stage ----
    auto compute = [&](int k){
        const float* st = wsm + ((k & 1) * STAGE_BYTES) / 4;
        const float* Lr = st + 16 * xq;
        const float* Rr = st + CC * LROW + rb;
        #pragma unroll 2
        for (int cc = 0; cc < CC; cc++){
            float l[16];
            #pragma unroll
            for (int t = 0; t < 4; t++)
                *(float4*)(l + 4*t) = *(const float4*)(Lr + cc * LROW + 4*t);
            float r[28];
            #pragma unroll
            for (int t = 0; t < 7; t++)
                *(float4*)(r + 4*t) = *(const float4*)(Rr + cc * RROW + 4*t);

            ull l2[8];
            #pragma unroll
            for (int u = 0; u < 8; u++) l2[u] = pack2(l[2*u], l[2*u+1]);
            ull e2[14];                 // aligned R pairs (even disparities)
            #pragma unroll
            for (int p = 1; p < 14; p++) e2[p] = pack2(r[2*p], r[2*p+1]);
            ull m2[13];                 // misaligned R pairs (odd disparities)
            #pragma unroll
            for (int p = 0; p < 13; p++) m2[p] = pack2(r[2*p+1], r[2*p+2]);

            // even a = 2*a2: pair index u + 6 - a2
            #pragma unroll
            for (int a2 = 0; a2 < 6; a2++)
                #pragma unroll
                for (int u = 0; u < 8; u++)
                    fma2(acc[2*a2][u], l2[u], e2[u + 6 - a2]);
            // odd a = 2*ao+1: pair index u + 5 - ao
            #pragma unroll
            for (int ao = 0; ao < 6; ao++)
                #pragma unroll
                for (int u = 0; u < 8; u++)
                    fma2(acc[2*ao+1][u], l2[u], m2[u + 5 - ao]);
        }
    };

    // ---- pipelined main loop ----
    issue(0);
    asm volatile("cp.async.commit_group;" ::: "memory");
    #pragma unroll 1
    for (int k = 0; k < NCHUNK; k++){
        if (k + 1 < NCHUNK){
            issue(k + 1);
            asm volatile("cp.async.commit_group;" ::: "memory");
            asm volatile("cp.async.wait_group 1;" ::: "memory");
        } else {
            asm volatile("cp.async.wait_group 0;" ::: "memory");
        }
        __syncwarp();
        compute(k);
        __syncwarp();
    }

    // ---- epilogue: scale by 1/128, coalesced 16B stores ----
    const ull s2 = pack2(1.0f/128.0f, 1.0f/128.0f);
    #pragma unroll
    for (int a = 0; a < 12; a++){
        const int i = i0 + a;
        float* dst = out + (((size_t)b * MAXD + i) * HH + h) * WW + X;
        #pragma unroll
        for (int t = 0; t < 4; t++){
            ull v0 = mul2(acc[a][2*t],     s2);
            ull v1 = mul2(acc[a][2*t + 1], s2);
            ulonglong2 v; v.x = v0; v.y = v1;
            *(ulonglong2*)(dst + 4 * t) = v;   // 16B store, 16B-aligned (X % 16 == 0)
        }
    }
}

extern "C" void kernel_launch(void* const* d_in, const int* in_sizes, int n_in,
                              void* d_out, int out_size)
{
    const float* L = (const float*)d_in[0];
    const float* R = (const float*)d_in[1];
    float* out = (float*)d_out;

    cudaFuncSetAttribute(costvol_f32x2_kernel,
                         cudaFuncAttributeMaxDynamicSharedMemorySize, SMEM_TOTAL);
    dim3 grid(BB * HH * 3 / NWARP);   // 2304 units / 4 warps = 576 CTAs
    costvol_f32x2_kernel<<<grid, 128, SMEM_TOTAL>>>(L, R, out);
}